// round 10
// baseline (speedup 1.0000x reference)
#include <cuda_runtime.h>
#include <math_constants.h>

// x [B=64, C=512, H=28, W=28] fp32; cc [B,28,28] bool widened to int32.
// out [B, 2C]: out[b,c]   = (sum_hw x[b,c,hw]*cc[b,hw] + x[b,c,0]) / max(cnt_b,1)
//              out[b,C+c] = max_hw x[b,c,hw]
//
// Warp-per-row, no smem/barriers (best R8 skeleton), but x is streamed with
// 256-bit LDG (ld.global.nc.v8.f32, sm_100+): 98 x 32B chunks per row =
// 3 warp-strides + 2-lane tail. Halves request count at constant bytes to
// test whether the ~4.9TB/s plateau is a per-request (MSHR) concurrency cap.

#define HW   784
#define C_DIM 512
#define THREADS 256
#define ROWS_PER_CTA 8

__device__ __forceinline__ void ldg256(const float* p, float4& lo, float4& hi)
{
    asm volatile(
        "ld.global.nc.v8.f32 {%0,%1,%2,%3,%4,%5,%6,%7}, [%8];"
        : "=f"(lo.x), "=f"(lo.y), "=f"(lo.z), "=f"(lo.w),
          "=f"(hi.x), "=f"(hi.y), "=f"(hi.z), "=f"(hi.w)
        : "l"(p));
}

__global__ __launch_bounds__(THREADS) void pool_kernel(
    const float* __restrict__ x,
    const int* __restrict__ cc,
    float* __restrict__ out)
{
    const int tid  = threadIdx.x;
    const int wid  = tid >> 5;
    const int lane = tid & 31;

    const int bc = blockIdx.x * ROWS_PER_CTA + wid;   // this warp's row
    const int b  = bc >> 9;

    const float* __restrict__ xrow = x + (size_t)bc * HW;
    const int4*  __restrict__ mr   = reinterpret_cast<const int4*>(cc + (size_t)b * HW);

    // ---- 1. Front-batch x loads: 98 chunks of 32B = 3*32 + 2 ----
    float4 lo[4], hi[4];
    #pragma unroll
    for (int j = 0; j < 3; j++)
        ldg256(xrow + 8 * (lane + 32 * j), lo[j], hi[j]);
    const bool tail = (lane < 2);
    if (tail)
        ldg256(xrow + 8 * (lane + 96), lo[3], hi[3]);

    // ---- 2. Consume with mask int4 loads (L1/L2 hits) ----
    float sum0 = 0.0f, sum1 = 0.0f;
    int   icnt = 0;
    float mx   = -CUDART_INF_F;

    #pragma unroll
    for (int j = 0; j < 3; j++) {
        const int c8 = lane + 32 * j;          // 8-float chunk index
        int4 m0 = mr[2 * c8];
        int4 m1 = mr[2 * c8 + 1];
        sum0 += (m0.x ? lo[j].x : 0.0f) + (m0.y ? lo[j].y : 0.0f)
              + (m0.z ? lo[j].z : 0.0f) + (m0.w ? lo[j].w : 0.0f);
        sum1 += (m1.x ? hi[j].x : 0.0f) + (m1.y ? hi[j].y : 0.0f)
              + (m1.z ? hi[j].z : 0.0f) + (m1.w ? hi[j].w : 0.0f);
        icnt += (m0.x != 0) + (m0.y != 0) + (m0.z != 0) + (m0.w != 0)
              + (m1.x != 0) + (m1.y != 0) + (m1.z != 0) + (m1.w != 0);
        float mxa = fmaxf(fmaxf(lo[j].x, lo[j].y), fmaxf(lo[j].z, lo[j].w));
        float mxb = fmaxf(fmaxf(hi[j].x, hi[j].y), fmaxf(hi[j].z, hi[j].w));
        mx = fmaxf(mx, fmaxf(mxa, mxb));
    }
    if (tail) {
        const int c8 = lane + 96;
        int4 m0 = mr[2 * c8];
        int4 m1 = mr[2 * c8 + 1];
        sum0 += (m0.x ? lo[3].x : 0.0f) + (m0.y ? lo[3].y : 0.0f)
              + (m0.z ? lo[3].z : 0.0f) + (m0.w ? lo[3].w : 0.0f);
        sum1 += (m1.x ? hi[3].x : 0.0f) + (m1.y ? hi[3].y : 0.0f)
              + (m1.z ? hi[3].z : 0.0f) + (m1.w ? hi[3].w : 0.0f);
        icnt += (m0.x != 0) + (m0.y != 0) + (m0.z != 0) + (m0.w != 0)
              + (m1.x != 0) + (m1.y != 0) + (m1.z != 0) + (m1.w != 0);
        float mxa = fmaxf(fmaxf(lo[3].x, lo[3].y), fmaxf(lo[3].z, lo[3].w));
        float mxb = fmaxf(fmaxf(hi[3].x, hi[3].y), fmaxf(hi[3].z, hi[3].w));
        mx = fmaxf(mx, fmaxf(mxa, mxb));
    }

    // ---- 3. Warp reduce ----
    float sum = sum0 + sum1;
    #pragma unroll
    for (int off = 16; off > 0; off >>= 1) {
        sum  += __shfl_down_sync(0xffffffffu, sum, off);
        icnt += __shfl_down_sync(0xffffffffu, icnt, off);
        mx    = fmaxf(mx, __shfl_down_sync(0xffffffffu, mx, off));
    }

    if (lane == 0) {
        const int c = bc & (C_DIM - 1);
        sum += lo[0].x;                      // + x[b,c,0,0] quirk: lane0 chunk0
        float denom = (icnt == 0) ? 1.0f : (float)icnt;
        out[(size_t)b * (2 * C_DIM) + c]         = sum / denom;
        out[(size_t)b * (2 * C_DIM) + C_DIM + c] = mx;
    }
}

extern "C" void kernel_launch(void* const* d_in, const int* in_sizes, int n_in,
                              void* d_out, int out_size)
{
    const float* x  = (const float*)d_in[0];
    const int*   cc = (const int*)d_in[1];
    float*       o  = (float*)d_out;

    pool_kernel<<<(64 * C_DIM) / ROWS_PER_CTA, THREADS>>>(x, cc, o);
}

// round 11
// speedup vs baseline: 1.1086x; 1.1086x over previous
#include <cuda_runtime.h>
#include <math_constants.h>
#include <cstdint>

// x [B=64, C=512, H=28, W=28] fp32; cc [B,28,28] bool widened to int32.
// out [B, 2C]: out[b,c]   = (sum_hw x[b,c,hw]*cc[b,hw] + x[b,c,0]) / max(cnt_b,1)
//              out[b,C+c] = max_hw x[b,c,hw]
//
// TMA-bulk streamer: CTA owns 32 contiguous rows. Thread 0 issues FOUR 25KB
// cp.async.bulk copies (one per 8-row chunk) back-to-back -> 100KB in flight
// per CTA (200KB/SM), bypassing the L1tex LDG queue that capped all previous
// variants at ~4.9TB/s. 8 warps consume warp-per-row from smem (LDS.128,
// conflict-free); mask via int4 LDG (L1-resident). One mbarrier per chunk,
// phase 0 only, no buffer reuse.

#define HW           784
#define C_DIM        512
#define THREADS      256
#define ROWS_PER_CTA 32
#define CHUNK_ROWS   8
#define NCHUNK       4
#define CHUNK_BYTES  (CHUNK_ROWS * HW * 4)          // 25088
#define SMEM_TOTAL   (128 + NCHUNK * CHUNK_BYTES)   // 100480

__device__ __forceinline__ uint32_t smem_u32(const void* p) {
    uint32_t a;
    asm("{ .reg .u64 t; cvta.to.shared.u64 t, %1; cvt.u32.u64 %0, t; }"
        : "=r"(a) : "l"(p));
    return a;
}

__device__ __forceinline__ void mbar_wait(uint32_t mbar, uint32_t parity) {
    asm volatile(
        "{\n\t"
        ".reg .pred P;\n\t"
        "WAIT_%=:\n\t"
        "mbarrier.try_wait.parity.shared.b64 P, [%0], %1;\n\t"
        "@!P bra WAIT_%=;\n\t"
        "}" :: "r"(mbar), "r"(parity) : "memory");
}

__global__ __launch_bounds__(THREADS) void pool_kernel(
    const float* __restrict__ x,
    const int* __restrict__ cc,
    float* __restrict__ out)
{
    extern __shared__ __align__(128) char smem[];
    const uint32_t sbase = smem_u32(smem);
    const uint32_t mbar  = sbase;                 // 4 x 8B barriers
    float* __restrict__ sdata = reinterpret_cast<float*>(smem + 128);
    const uint32_t sdata_u = sbase + 128;

    const int tid  = threadIdx.x;
    const int wid  = tid >> 5;
    const int lane = tid & 31;

    const int bc0 = blockIdx.x * ROWS_PER_CTA;    // 32 contiguous rows
    const int b   = bc0 >> 9;                     // same batch (32 | 512)

    if (tid == 0) {
        #pragma unroll
        for (int c = 0; c < NCHUNK; c++)
            asm volatile("mbarrier.init.shared.b64 [%0], 1;"
                         :: "r"(mbar + 8u * c) : "memory");
        asm volatile("fence.proxy.async.shared::cta;" ::: "memory");
    }
    __syncthreads();

    if (tid == 0) {
        const char* src = reinterpret_cast<const char*>(x + (size_t)bc0 * HW);
        #pragma unroll
        for (int c = 0; c < NCHUNK; c++) {
            asm volatile("mbarrier.arrive.expect_tx.shared.b64 _, [%0], %1;"
                         :: "r"(mbar + 8u * c), "r"((uint32_t)CHUNK_BYTES)
                         : "memory");
            asm volatile(
                "cp.async.bulk.shared::cta.global.mbarrier::complete_tx::bytes "
                "[%0], [%1], %2, [%3];"
                :: "r"(sdata_u + (uint32_t)c * CHUNK_BYTES),
                   "l"(src + (size_t)c * CHUNK_BYTES),
                   "r"((uint32_t)CHUNK_BYTES),
                   "r"(mbar + 8u * c)
                : "memory");
        }
    }

    const int4* __restrict__ mr =
        reinterpret_cast<const int4*>(cc + (size_t)b * HW);

    #pragma unroll
    for (int c = 0; c < NCHUNK; c++) {
        mbar_wait(mbar + 8u * c, 0);

        const int r  = c * CHUNK_ROWS + wid;      // row within CTA
        const int bc = bc0 + r;
        const float4* __restrict__ xr =
            reinterpret_cast<const float4*>(sdata + (size_t)r * HW);

        float sum0 = 0.0f, sum1 = 0.0f;
        int   icnt = 0;
        float mx   = -CUDART_INF_F;

        #pragma unroll
        for (int j = 0; j < 6; j++) {
            float4 v = xr[lane + 32 * j];         // LDS.128, conflict-free
            int4   m = mr[lane + 32 * j];         // LDG, L1-resident
            sum0 += (m.x ? v.x : 0.0f) + (m.y ? v.y : 0.0f);
            sum1 += (m.z ? v.z : 0.0f) + (m.w ? v.w : 0.0f);
            icnt += (m.x != 0) + (m.y != 0) + (m.z != 0) + (m.w != 0);
            mx = fmaxf(mx, fmaxf(fmaxf(v.x, v.y), fmaxf(v.z, v.w)));
        }
        if (lane < 4) {
            float4 v = xr[lane + 192];
            int4   m = mr[lane + 192];
            sum0 += (m.x ? v.x : 0.0f) + (m.y ? v.y : 0.0f);
            sum1 += (m.z ? v.z : 0.0f) + (m.w ? v.w : 0.0f);
            icnt += (m.x != 0) + (m.y != 0) + (m.z != 0) + (m.w != 0);
            mx = fmaxf(mx, fmaxf(fmaxf(v.x, v.y), fmaxf(v.z, v.w)));
        }

        float sum = sum0 + sum1;
        #pragma unroll
        for (int off = 16; off > 0; off >>= 1) {
            sum  += __shfl_down_sync(0xffffffffu, sum, off);
            icnt += __shfl_down_sync(0xffffffffu, icnt, off);
            mx    = fmaxf(mx, __shfl_down_sync(0xffffffffu, mx, off));
        }

        if (lane == 0) {
            const int cch = bc & (C_DIM - 1);
            sum += xr[0].x;                       // + x[b,c,0,0] quirk (smem)
            float denom = (icnt == 0) ? 1.0f : (float)icnt;
            out[(size_t)b * (2 * C_DIM) + cch]         = sum / denom;
            out[(size_t)b * (2 * C_DIM) + C_DIM + cch] = mx;
        }
    }
}

extern "C" void kernel_launch(void* const* d_in, const int* in_sizes, int n_in,
                              void* d_out, int out_size)
{
    const float* x  = (const float*)d_in[0];
    const int*   cc = (const int*)d_in[1];
    float*       o  = (float*)d_out;

    cudaFuncSetAttribute(pool_kernel,
                         cudaFuncAttributeMaxDynamicSharedMemorySize,
                         SMEM_TOTAL);

    // grid = 32768 rows / 32 rows per CTA = 1024
    pool_kernel<<<(64 * C_DIM) / ROWS_PER_CTA, THREADS, SMEM_TOTAL>>>(x, cc, o);
}